// round 10
// baseline (speedup 1.0000x reference)
#include <cuda_runtime.h>
#include <float.h>

#define BB   64
#define DD   64
#define TTm  4096
#define KKm  512
#define TILE 128
#define NTH  256
#define N_ELEM ((size_t)BB * DD * TTm)

// smem byte offsets
#define SM_X2    0         // 128 f
#define SM_C2    512       // 512 f
#define SM_GT    2560      // 128 f (per-token gate threshold)
#define SM_MV    3072      // 128 f (per-token -2/(Sz*Se) fold scale)
#define SM_KIDX  3584      // 128 i
#define SM_QUE   4096      // 128 i
#define SM_WRED  4608      // 8 f
#define SM_QCNT  4640      // 1 i
#define SM_ZS    4736      // 128x64 f32 [d][t]        (32768 B)
#define SM_ZQ    37504     // int32 [quad 0..15][tok]  (8192 B)
#define SM_EQ    45696     // int32 [quad 0..15][code] (32768 B)
#define SM_TOTAL 78464

__device__ double g_loss;
__device__ float  g_c2[KKm];
__device__ int    g_eq[16 * KKm];   // packed int8 codebook, [quad][code]

// ---------------------------------------------------------------------------
// prep: c2 (rounded squares + pairwise tree, reference numerics) + int8 emb
// ---------------------------------------------------------------------------
__global__ void vq_prep(const float* __restrict__ emb) {
    int k = threadIdx.x;
    if (k == 0) g_loss = 0.0;
    if (k < KKm) {
        const float* e = emb + k * DD;
        float p[DD];
        #pragma unroll
        for (int d = 0; d < DD; d++) { float v = e[d]; p[d] = __fmul_rn(v, v); }
        #pragma unroll
        for (int w = DD; w > 1; w >>= 1)
            #pragma unroll
            for (int i = 0; i < DD / 2; i++)
                if (i < w / 2) p[i] = __fadd_rn(p[2 * i], p[2 * i + 1]);
        g_c2[k] = p[0];
        // int8 quantization: |e| < 1/512 -> |e*65024| < 127 (no clamp needed)
        #pragma unroll
        for (int q = 0; q < 16; q++) {
            unsigned w4 = 0;
            #pragma unroll
            for (int u = 0; u < 4; u++) {
                int i8 = __float2int_rn(e[q * 4 + u] * 65024.f);
                w4 |= ((unsigned)(i8 & 0xFF)) << (u * 8);
            }
            g_eq[q * KKm + k] = (int)w4;
        }
    }
}

// ---------------------------------------------------------------------------
// main: int8 dp4a screening GEMM + hard-bound gate + exact rescue + epilogue
// ---------------------------------------------------------------------------
__global__ __launch_bounds__(NTH, 2)
void vq_main(const float* __restrict__ z, const float* __restrict__ emb,
             float* __restrict__ out) {
    extern __shared__ char smem[];
    const int tid  = threadIdx.x;
    const int wid  = tid >> 5, lane = tid & 31;
    const int tile = blockIdx.x, b = tile >> 5, t0 = (tile & 31) * TILE;
    const size_t zbase = (size_t)b * DD * TTm + t0;

    float* zs   = (float*)(smem + SM_ZS);
    float* x2s  = (float*)(smem + SM_X2);
    float* c2s  = (float*)(smem + SM_C2);
    float* gts  = (float*)(smem + SM_GT);
    float* mvs  = (float*)(smem + SM_MV);
    int*   zqs  = (int*)(smem + SM_ZQ);
    int*   eqs  = (int*)(smem + SM_EQ);
    int*   kidx = (int*)(smem + SM_KIDX);
    int*   que  = (int*)(smem + SM_QUE);
    float* wred = (float*)(smem + SM_WRED);
    int*   qcnt = (int*)(smem + SM_QCNT);

    if (tid == 0) *qcnt = 0;

    // ---- load z tile fp32 [d][t] coalesced; c2; int8 codebook ----
    for (int i = tid; i < DD * TILE / 4; i += NTH) {
        int row = i >> 5, col = (i & 31) << 2;
        *(float4*)(zs + row * TILE + col) =
            *(const float4*)(z + zbase + (size_t)row * TTm + col);
    }
    for (int i = tid; i < KKm; i += NTH) c2s[i] = g_c2[i];
    for (int i = tid; i < 16 * KKm / 4; i += NTH)
        *(int4*)(eqs + i * 4) = *(const int4*)(g_eq + i * 4);
    __syncthreads();

    // ---- per-token quantization + exact x2 chain + hard error bound ----
    if (tid < TILE) {
        float vmax = 1e-6f;
        #pragma unroll
        for (int d = 0; d < DD; d++) vmax = fmaxf(vmax, fabsf(zs[d * TILE + tid]));
        float S    = 126.f / vmax;
        float invS = vmax * (1.f / 126.f);
        float s = 0.f, adz = 0.f;
        int ai8 = 0;
        #pragma unroll
        for (int q = 0; q < 16; q++) {
            unsigned w4 = 0;
            #pragma unroll
            for (int u = 0; u < 4; u++) {
                float v = zs[(q * 4 + u) * TILE + tid];
                s = fmaf(v, v, s);                    // reference x2 chain
                int i8 = __float2int_rn(v * S);
                i8 = max(-127, min(127, i8));
                adz += fabsf(fmaf((float)i8, -invS, v));
                ai8 += abs(i8);
                w4 |= ((unsigned)(i8 & 0xFF)) << (u * 8);
            }
            zqs[q * TILE + tid] = (int)w4;
        }
        x2s[tid] = s;
        mvs[tid] = (-2.f / 65024.f) * invS;
        // gate = 2*(emax*sum|dz| + de_max*sum|zhat|) + fp32 fold margin
        gts[tid] = fmaf(2.f, fmaf(1.953125e-3f, adz,
                                  7.6894e-6f * invS * (float)ai8), 5e-5f);
    }
    __syncthreads();

    // ---- approx GEMM: warp owns 16 tokens, lane strides codes by 32 ----
    #pragma unroll 1
    for (int h = 0; h < 2; h++) {
        const int tb = wid * 16 + h * 8;
        float x2r[8], mvr[8];
        #pragma unroll
        for (int i = 0; i < 8; i++) { x2r[i] = x2s[tb + i]; mvr[i] = mvs[tb + i]; }
        float d1[8], d2[8]; int k1[8];
        #pragma unroll
        for (int i = 0; i < 8; i++) { d1[i] = FLT_MAX; d2[i] = FLT_MAX; k1[i] = 0; }

        #pragma unroll 1
        for (int p = 0; p < 4; p++) {
            const int cbase = p * 128 + lane;
            int acc[8][4];
            #pragma unroll
            for (int i = 0; i < 8; i++)
                #pragma unroll
                for (int j = 0; j < 4; j++) acc[i][j] = 0;

            #pragma unroll
            for (int q = 0; q < 16; q++) {
                int zv[8], ev[4];
                #pragma unroll
                for (int i = 0; i < 8; i++) zv[i] = zqs[q * TILE + tb + i];
                #pragma unroll
                for (int j = 0; j < 4; j++) ev[j] = eqs[q * KKm + cbase + j * 32];
                #pragma unroll
                for (int j = 0; j < 4; j++)
                    #pragma unroll
                    for (int i = 0; i < 8; i++)
                        acc[i][j] = __dp4a(zv[i], ev[j], acc[i][j]);
            }
            #pragma unroll
            for (int j = 0; j < 4; j++) {
                int code = cbase + j * 32;
                float c2v = c2s[code];
                #pragma unroll
                for (int i = 0; i < 8; i++) {
                    float v = fmaf((float)acc[i][j], mvr[i], x2r[i] + c2v);
                    if (v < d1[i]) { d2[i] = d1[i]; d1[i] = v; k1[i] = code; }
                    else if (v < d2[i]) d2[i] = v;
                }
            }
        }

        // butterfly allreduce of (d1,k1,d2) across 32 lanes
        #pragma unroll
        for (int off = 16; off > 0; off >>= 1) {
            #pragma unroll
            for (int i = 0; i < 8; i++) {
                float od1 = __shfl_xor_sync(0xffffffffu, d1[i], off);
                int   ok1 = __shfl_xor_sync(0xffffffffu, k1[i], off);
                float od2 = __shfl_xor_sync(0xffffffffu, d2[i], off);
                if (od1 < d1[i] || (od1 == d1[i] && ok1 < k1[i])) {
                    d2[i] = fminf(d1[i], od2); d1[i] = od1; k1[i] = ok1;
                } else {
                    d2[i] = fminf(d2[i], od1);
                }
            }
        }
        if (lane == 0) {
            #pragma unroll
            for (int i = 0; i < 8; i++)
                kidx[tb + i] = (d2[i] - d1[i] > gts[tb + i]) ? k1[i] : -1;
        }
    }
    __syncthreads();

    // ---- queue ambiguous tokens ----
    if (tid < TILE && kidx[tid] < 0) {
        int pos = atomicAdd(qcnt, 1);
        que[pos] = tid;
    }
    __syncthreads();

    // ---- warp-cooperative exact rescue (reference-rounded, lexicographic) ----
    const int qc = *qcnt;
    for (int q = wid; q < qc; q += NTH / 32) {
        int tok = que[q];
        float x2 = x2s[tok];
        float s[16];
        #pragma unroll
        for (int cc = 0; cc < 16; cc++) s[cc] = 0.f;
        #pragma unroll
        for (int chunk = 0; chunk < 4; chunk++) {
            float zv[16];
            #pragma unroll
            for (int dd = 0; dd < 16; dd++) zv[dd] = zs[(chunk * 16 + dd) * TILE + tok];
            #pragma unroll
            for (int cc = 0; cc < 16; cc++) {
                const float* e = emb + (lane * 16 + cc) * DD + chunk * 16;
                #pragma unroll
                for (int dq = 0; dq < 4; dq++) {
                    float4 ev = __ldg((const float4*)(e + dq * 4));
                    s[cc] = fmaf(zv[dq * 4 + 0], ev.x, s[cc]);
                    s[cc] = fmaf(zv[dq * 4 + 1], ev.y, s[cc]);
                    s[cc] = fmaf(zv[dq * 4 + 2], ev.z, s[cc]);
                    s[cc] = fmaf(zv[dq * 4 + 3], ev.w, s[cc]);
                }
            }
        }
        float bd = FLT_MAX; int bk = 0;
        #pragma unroll
        for (int cc = 0; cc < 16; cc++) {
            int code = lane * 16 + cc;
            float dd = __fsub_rn(__fadd_rn(x2, c2s[code]), __fmul_rn(2.f, s[cc]));
            if (dd < bd) { bd = dd; bk = code; }
        }
        #pragma unroll
        for (int off = 16; off > 0; off >>= 1) {
            float od = __shfl_down_sync(0xffffffffu, bd, off);
            int   ok = __shfl_down_sync(0xffffffffu, bk, off);
            if (od < bd || (od == bd && ok < bk)) { bd = od; bk = ok; }
        }
        if (lane == 0) kidx[tok] = bk;
    }
    __syncthreads();

    // ---- gather + straight-through output + loss (reference rounding) ----
    float lsum = 0.f;
    for (int i = tid; i < DD * TILE; i += NTH) {
        int d = i >> 7, tt = i & 127;
        float q  = __ldg(emb + kidx[tt] * DD + d);
        float zv = zs[d * TILE + tt];
        float diff = __fsub_rn(q, zv);
        out[zbase + (size_t)d * TTm + tt] = __fadd_rn(zv, diff);
        lsum = fmaf(diff, diff, lsum);
    }
    #pragma unroll
    for (int o = 16; o > 0; o >>= 1)
        lsum += __shfl_down_sync(0xffffffffu, lsum, o);
    if (lane == 0) wred[wid] = lsum;
    __syncthreads();
    if (tid == 0) {
        float sacc = 0.f;
        #pragma unroll
        for (int w = 0; w < NTH / 32; w++) sacc += wred[w];
        atomicAdd(&g_loss, (double)sacc);
    }
}

// ---------------------------------------------------------------------------
__global__ void vq_fin(float* __restrict__ out) {
    double m = g_loss / (double)N_ELEM;
    out[N_ELEM]     = (float)m;
    out[N_ELEM + 1] = (float)(0.25 * m);
}

// ---------------------------------------------------------------------------
extern "C" void kernel_launch(void* const* d_in, const int* in_sizes, int n_in,
                              void* d_out, int out_size) {
    const float* z   = (const float*)d_in[0];
    const float* emb = (const float*)d_in[1];
    float*       out = (float*)d_out;

    (void)cudaFuncSetAttribute(vq_main,
                               cudaFuncAttributeMaxDynamicSharedMemorySize,
                               SM_TOTAL);

    vq_prep<<<1, 512>>>(emb);
    vq_main<<<(BB * TTm) / TILE, NTH, SM_TOTAL>>>(z, emb, out);
    vq_fin<<<1, 1>>>(out);
}

// round 11
// speedup vs baseline: 5.3726x; 5.3726x over previous
#include <cuda_runtime.h>
#include <float.h>

// Problem constants
#define BB   64
#define DD   64
#define TTm  4096
#define KKm  512
#define TILE 128      // tokens per CTA
#define KCH  128      // codes per chunk
#define ESP  132      // padded smem stride for transposed emb chunk
#define NTH  256

#define N_ELEM ((size_t)BB * DD * TTm)   // 16777216

// dynamic smem (floats): zs + es + c2s + x2s + rd + rk + kidx + wred
#define SMEM_FLOATS (DD*TILE + DD*ESP + KCH + TILE + TILE*17 + TILE*17 + TILE + NTH/32)
#define SMEM_BYTES  (SMEM_FLOATS * 4)

__device__ double g_loss;
__device__ float  g_c2[KKm];

// ---------------------------------------------------------------------------
// prep: codebook squared norms (rounded squares + pairwise tree, reference
// numerics) + zero the loss accumulator. Runs every launch (graph-safe).
// ---------------------------------------------------------------------------
__global__ void vq_prep(const float* __restrict__ emb) {
    int k = threadIdx.x;
    if (k == 0) g_loss = 0.0;
    if (k < KKm) {
        const float* e = emb + k * DD;
        float p[DD];
        #pragma unroll
        for (int d = 0; d < DD; d++) {
            float v = e[d];
            p[d] = __fmul_rn(v, v);
        }
        #pragma unroll
        for (int w = DD; w > 1; w >>= 1) {
            #pragma unroll
            for (int i = 0; i < DD / 2; i++) {
                if (i < w / 2) p[i] = __fadd_rn(p[2 * i], p[2 * i + 1]);
            }
        }
        g_c2[k] = p[0];
    }
}

// ---------------------------------------------------------------------------
// main: fused distance GEMM (scalar fp32 FFMA, 8x8 register tile) + argmin
//       + gather + straight-through + loss. Reference rounding throughout:
//   d = fl( fl(x2 + c2) - fl(2 * dot) ), dot = ascending-k fp32 fma chain.
// ---------------------------------------------------------------------------
__global__ __launch_bounds__(NTH, 2)
void vq_main(const float* __restrict__ z, const float* __restrict__ emb,
             float* __restrict__ out) {
    extern __shared__ float smem[];
    float* zs   = smem;                       // 64*128
    float* es   = zs + DD * TILE;             // 64*132
    float* c2s  = es + DD * ESP;              // 128
    float* x2s  = c2s + KCH;                  // 128
    float* rd   = x2s + TILE;                 // 128*17
    int*   rk   = (int*)(rd + TILE * 17);     // 128*17
    int*   kidx = rk + TILE * 17;             // 128
    float* wred = (float*)(kidx + TILE);      // 8

    const int tid = threadIdx.x;
    const int tx  = tid & 15;       // code-column group (8 codes)
    const int ty  = tid >> 4;       // token-row group (8 tokens)
    const int tile = blockIdx.x;
    const int b    = tile >> 5;
    const int t0   = (tile & 31) * TILE;
    const size_t zbase = (size_t)b * DD * TTm + t0;

    // ---- load z tile [64 dims x 128 tokens], coalesced float4 ----
    for (int i = tid; i < DD * TILE / 4; i += NTH) {
        int row = i >> 5;
        int col = (i & 31) << 2;
        float4 v = *(const float4*)(z + zbase + (size_t)row * TTm + col);
        *(float4*)(zs + row * TILE + col) = v;
    }
    __syncthreads();

    // ---- per-token ||x||^2 (ascending-d fma chain; constant shift of all
    // 512 distances => argmin-order invariant) ----
    if (tid < TILE) {
        float s = 0.f;
        #pragma unroll
        for (int d = 0; d < DD; d++) {
            float v = zs[d * TILE + tid];
            s = fmaf(v, v, s);
        }
        x2s[tid] = s;
    }

    float bestd[8];
    int   bestk[8];
    #pragma unroll
    for (int i = 0; i < 8; i++) { bestd[i] = FLT_MAX; bestk[i] = 0; }

    #pragma unroll 1
    for (int c = 0; c < KKm / KCH; c++) {
        __syncthreads();   // prev chunk compute done; publishes x2s on c=0
        // load emb chunk transposed: es[d][kk] = emb[c*128+kk][d]
        for (int i = tid; i < KCH * DD / 4; i += NTH) {
            int kk = i >> 4;
            int dq = (i & 15) << 2;
            float4 v = *(const float4*)(emb + (size_t)(c * KCH + kk) * DD + dq);
            es[(dq + 0) * ESP + kk] = v.x;
            es[(dq + 1) * ESP + kk] = v.y;
            es[(dq + 2) * ESP + kk] = v.z;
            es[(dq + 3) * ESP + kk] = v.w;
        }
        if (tid < KCH) c2s[tid] = g_c2[c * KCH + tid];
        __syncthreads();

        float acc[8][8];
        #pragma unroll
        for (int i = 0; i < 8; i++)
            #pragma unroll
            for (int j = 0; j < 8; j++) acc[i][j] = 0.f;

        // scalar fp32 mainloop: 4x LDS.128 + 64 FFMA per d, no packing
        #pragma unroll 4
        for (int d = 0; d < DD; d++) {
            float4 a0 = *(const float4*)(zs + d * TILE + ty * 8);
            float4 a1 = *(const float4*)(zs + d * TILE + ty * 8 + 4);
            float4 b0 = *(const float4*)(es + d * ESP + tx * 8);
            float4 b1 = *(const float4*)(es + d * ESP + tx * 8 + 4);
            float av[8] = {a0.x, a0.y, a0.z, a0.w, a1.x, a1.y, a1.z, a1.w};
            float bv[8] = {b0.x, b0.y, b0.z, b0.w, b1.x, b1.y, b1.z, b1.w};
            #pragma unroll
            for (int j = 0; j < 8; j++)
                #pragma unroll
                for (int i = 0; i < 8; i++)
                    acc[i][j] = fmaf(av[i], bv[j], acc[i][j]);
        }

        // chunk epilogue: d = fl( fl(x2+c2) - fl(2*dot) ), predicated argmin
        float x2r[8];
        #pragma unroll
        for (int i = 0; i < 8; i++) x2r[i] = x2s[ty * 8 + i];
        #pragma unroll
        for (int j = 0; j < 8; j++) {
            float c2v = c2s[tx * 8 + j];
            int   kg  = c * KCH + tx * 8 + j;
            #pragma unroll
            for (int i = 0; i < 8; i++) {
                float A  = __fadd_rn(x2r[i], c2v);
                float dv = __fsub_rn(A, __fmul_rn(2.0f, acc[i][j]));
                bool  lt = dv < bestd[i];
                bestd[i] = lt ? dv : bestd[i];
                bestk[i] = lt ? kg : bestk[i];
            }
        }
    }

    // ---- cross-thread argmin reduce (16 code-groups per token) ----
    #pragma unroll
    for (int i = 0; i < 8; i++) {
        int tok = ty * 8 + i;
        rd[tok * 17 + tx] = bestd[i];
        rk[tok * 17 + tx] = bestk[i];
    }
    __syncthreads();
    if (tid < TILE) {
        float bd = rd[tid * 17];
        int   bk = rk[tid * 17];
        #pragma unroll
        for (int x = 1; x < 16; x++) {
            float dv = rd[tid * 17 + x];
            int   kv = rk[tid * 17 + x];
            if (dv < bd || (dv == bd && kv < bk)) { bd = dv; bk = kv; }
        }
        kidx[tid] = bk;
    }
    __syncthreads();

    // ---- gather + straight-through output + loss (reference rounding) ----
    float lsum = 0.f;
    for (int i = tid; i < DD * TILE; i += NTH) {
        int d = i >> 7;
        int t = i & 127;
        float q  = __ldg(emb + kidx[t] * DD + d);
        float zv = zs[d * TILE + t];
        float diff = __fsub_rn(q, zv);
        out[zbase + (size_t)d * TTm + t] = __fadd_rn(zv, diff);
        lsum = fmaf(diff, diff, lsum);
    }
    #pragma unroll
    for (int o = 16; o > 0; o >>= 1)
        lsum += __shfl_down_sync(0xffffffffu, lsum, o);
    if ((tid & 31) == 0) wred[tid >> 5] = lsum;
    __syncthreads();
    if (tid == 0) {
        float s = 0.f;
        #pragma unroll
        for (int w = 0; w < NTH / 32; w++) s += wred[w];
        atomicAdd(&g_loss, (double)s);
    }
}

// ---------------------------------------------------------------------------
// finalize: write the two loss scalars
// ---------------------------------------------------------------------------
__global__ void vq_fin(float* __restrict__ out) {
    double m = g_loss / (double)N_ELEM;
    out[N_ELEM]     = (float)m;           // vq_loss = mean((q - z)^2)
    out[N_ELEM + 1] = (float)(0.25 * m);  // commitment = 0.25 * same mean
}

// ---------------------------------------------------------------------------
extern "C" void kernel_launch(void* const* d_in, const int* in_sizes, int n_in,
                              void* d_out, int out_size) {
    const float* z   = (const float*)d_in[0];
    const float* emb = (const float*)d_in[1];
    float*       out = (float*)d_out;

    (void)cudaFuncSetAttribute(vq_main,
                               cudaFuncAttributeMaxDynamicSharedMemorySize,
                               SMEM_BYTES);

    vq_prep<<<1, 512>>>(emb);
    vq_main<<<(BB * TTm) / TILE, NTH, SMEM_BYTES>>>(z, emb, out);
    vq_fin<<<1, 1>>>(out);
}

// round 13
// speedup vs baseline: 5.6774x; 1.0567x over previous
#include <cuda_runtime.h>
#include <float.h>

// Problem constants
#define BB   64
#define DD   64
#define TTm  4096
#define KKm  512
#define TILE 128      // tokens per CTA
#define KCH  128      // codes per chunk
#define ESP  132      // padded smem stride for transposed emb chunk
#define NTH  256
#define GRID ((BB * TTm) / TILE)         // 2048

#define N_ELEM ((size_t)BB * DD * TTm)   // 16777216

// dynamic smem (floats): zs + es + c2s(512) + x2s + kidx + wred
#define SMEM_FLOATS (DD*TILE + DD*ESP + KKm + TILE + TILE + NTH/32)
#define SMEM_BYTES  (SMEM_FLOATS * 4)

__device__ double   g_loss;
__device__ unsigned g_done;     // zero-init; reset by last CTA each launch
__device__ float    g_c2[KKm];

// ---------------------------------------------------------------------------
// prep: codebook squared norms via 7-register stack fold == adjacent-pair
// balanced tree (bit-identical to the passing version, no local-mem spills).
// ---------------------------------------------------------------------------
__global__ void vq_prep(const float* __restrict__ emb) {
    int k = blockIdx.x * 64 + threadIdx.x;    // grid 8 x 64 = 512 codes
    if (k == 0) g_loss = 0.0;
    const float* e = emb + k * DD;
    float st[7];
    int sp = 0;
    #pragma unroll
    for (int d = 0; d < DD; d++) {
        float v = e[d];
        float cur = __fmul_rn(v, v);
        int m = d;
        while (m & 1) { cur = __fadd_rn(st[--sp], cur); m >>= 1; }
        st[sp++] = cur;
    }
    g_c2[k] = st[0];
}

// ---------------------------------------------------------------------------
// main: fused distance GEMM (scalar fp32 FFMA, 8x8 register tile) + shfl
//       argmin + gather + straight-through + loss + last-CTA finalize.
// Reference rounding: d = fl( fl(x2 + c2) - fl(2 * dot) ), ascending-k fma.
// ---------------------------------------------------------------------------
__global__ __launch_bounds__(NTH, 2)
void vq_main(const float* __restrict__ z, const float* __restrict__ emb,
             float* __restrict__ out) {
    extern __shared__ float smem[];
    float* zs   = smem;                       // 64*128
    float* es   = zs + DD * TILE;             // 64*132
    float* c2s  = es + DD * ESP;              // 512
    float* x2s  = c2s + KKm;                  // 128
    int*   kidx = (int*)(x2s + TILE);         // 128
    float* wred = (float*)(kidx + TILE);      // 8

    const int tid = threadIdx.x;
    const int tx  = tid & 15;       // code-column group (8 codes)
    const int ty  = tid >> 4;       // token-row group (8 tokens)
    const int tile = blockIdx.x;
    const int b    = tile >> 5;
    const int t0   = (tile & 31) * TILE;
    const size_t zbase = (size_t)b * DD * TTm + t0;

    // ---- load z tile [64 dims x 128 tokens] + full c2, coalesced ----
    for (int i = tid; i < DD * TILE / 4; i += NTH) {
        int row = i >> 5;
        int col = (i & 31) << 2;
        float4 v = *(const float4*)(z + zbase + (size_t)row * TTm + col);
        *(float4*)(zs + row * TILE + col) = v;
    }
    for (int i = tid; i < KKm; i += NTH) c2s[i] = g_c2[i];
    __syncthreads();

    // ---- per-token ||x||^2 (ascending-d fma chain; constant shift of all
    // 512 distances => argmin-order invariant) ----
    if (tid < TILE) {
        float s = 0.f;
        #pragma unroll
        for (int d = 0; d < DD; d++) {
            float v = zs[d * TILE + tid];
            s = fmaf(v, v, s);
        }
        x2s[tid] = s;
    }

    float bestd[8];
    int   bestk[8];
    #pragma unroll
    for (int i = 0; i < 8; i++) { bestd[i] = FLT_MAX; bestk[i] = 0; }

    #pragma unroll 1
    for (int c = 0; c < KKm / KCH; c++) {
        __syncthreads();   // prev chunk compute done; publishes x2s on c=0
        // load emb chunk transposed: es[d][kk] = emb[c*128+kk][d]
        for (int i = tid; i < KCH * DD / 4; i += NTH) {
            int kk = i >> 4;
            int dq = (i & 15) << 2;
            float4 v = *(const float4*)(emb + (size_t)(c * KCH + kk) * DD + dq);
            es[(dq + 0) * ESP + kk] = v.x;
            es[(dq + 1) * ESP + kk] = v.y;
            es[(dq + 2) * ESP + kk] = v.z;
            es[(dq + 3) * ESP + kk] = v.w;
        }
        __syncthreads();

        float acc[8][8];
        #pragma unroll
        for (int i = 0; i < 8; i++)
            #pragma unroll
            for (int j = 0; j < 8; j++) acc[i][j] = 0.f;

        // scalar fp32 mainloop: 4x LDS.128 + 64 FFMA per d, no packing
        #pragma unroll 4
        for (int d = 0; d < DD; d++) {
            float4 a0 = *(const float4*)(zs + d * TILE + ty * 8);
            float4 a1 = *(const float4*)(zs + d * TILE + ty * 8 + 4);
            float4 b0 = *(const float4*)(es + d * ESP + tx * 8);
            float4 b1 = *(const float4*)(es + d * ESP + tx * 8 + 4);
            float av[8] = {a0.x, a0.y, a0.z, a0.w, a1.x, a1.y, a1.z, a1.w};
            float bv[8] = {b0.x, b0.y, b0.z, b0.w, b1.x, b1.y, b1.z, b1.w};
            #pragma unroll
            for (int j = 0; j < 8; j++)
                #pragma unroll
                for (int i = 0; i < 8; i++)
                    acc[i][j] = fmaf(av[i], bv[j], acc[i][j]);
        }

        // chunk epilogue: d = fl( fl(x2+c2) - fl(2*dot) ), predicated argmin
        float x2r[8];
        #pragma unroll
        for (int i = 0; i < 8; i++) x2r[i] = x2s[ty * 8 + i];
        #pragma unroll
        for (int j = 0; j < 8; j++) {
            float c2v = c2s[c * KCH + tx * 8 + j];
            int   kg  = c * KCH + tx * 8 + j;
            #pragma unroll
            for (int i = 0; i < 8; i++) {
                float A  = __fadd_rn(x2r[i], c2v);
                float dv = __fsub_rn(A, __fmul_rn(2.0f, acc[i][j]));
                bool  lt = dv < bestd[i];
                bestd[i] = lt ? dv : bestd[i];
                bestk[i] = lt ? kg : bestk[i];
            }
        }
    }

    // ---- cross-tx argmin reduce: 16-lane butterfly shfl, (d,k) lexicographic
    // (tx = lane & 15; offsets 8/4/2/1 stay within the 16-lane group) ----
    #pragma unroll
    for (int off = 8; off > 0; off >>= 1) {
        #pragma unroll
        for (int i = 0; i < 8; i++) {
            float od = __shfl_xor_sync(0xffffffffu, bestd[i], off);
            int   ok = __shfl_xor_sync(0xffffffffu, bestk[i], off);
            if (od < bestd[i] || (od == bestd[i] && ok < bestk[i])) {
                bestd[i] = od; bestk[i] = ok;
            }
        }
    }
    if (tx == 0) {
        #pragma unroll
        for (int i = 0; i < 8; i++) kidx[ty * 8 + i] = bestk[i];
    }
    __syncthreads();

    // ---- gather + straight-through output + loss (reference rounding) ----
    float lsum = 0.f;
    for (int i = tid; i < DD * TILE; i += NTH) {
        int d = i >> 7;
        int t = i & 127;
        float q  = __ldg(emb + kidx[t] * DD + d);
        float zv = zs[d * TILE + t];
        float diff = __fsub_rn(q, zv);
        out[zbase + (size_t)d * TTm + t] = __fadd_rn(zv, diff);
        lsum = fmaf(diff, diff, lsum);
    }
    #pragma unroll
    for (int o = 16; o > 0; o >>= 1)
        lsum += __shfl_down_sync(0xffffffffu, lsum, o);
    if ((tid & 31) == 0) wred[tid >> 5] = lsum;
    __syncthreads();
    if (tid == 0) {
        float s = 0.f;
        #pragma unroll
        for (int w = 0; w < NTH / 32; w++) s += wred[w];
        atomicAdd(&g_loss, (double)s);
        // last CTA to finish writes the loss scalars and resets the counter
        __threadfence();
        unsigned n = atomicAdd(&g_done, 1u);
        if (n == GRID - 1) {
            double m = g_loss / (double)N_ELEM;
            out[N_ELEM]     = (float)m;           // vq_loss
            out[N_ELEM + 1] = (float)(0.25 * m);  // commitment
            g_done = 0;                           // ready for next replay
        }
    }
}

// ---------------------------------------------------------------------------
extern "C" void kernel_launch(void* const* d_in, const int* in_sizes, int n_in,
                              void* d_out, int out_size) {
    const float* z   = (const float*)d_in[0];
    const float* emb = (const float*)d_in[1];
    float*       out = (float*)d_out;

    (void)cudaFuncSetAttribute(vq_main,
                               cudaFuncAttributeMaxDynamicSharedMemorySize,
                               SMEM_BYTES);

    vq_prep<<<8, 64>>>(emb);
    vq_main<<<GRID, NTH, SMEM_BYTES>>>(z, emb, out);
}